// round 2
// baseline (speedup 1.0000x reference)
#include <cuda_runtime.h>

#define B_    4
#define C_    128
#define W_    128
#define H_    128
#define DWIN  21
#define PADN  10
#define KC    8          // channels staged per smem chunk
#define NWARP 7          // di values per block (one per warp); 21 = 3 groups * 7
#define THREADS (NWARP * 32)
#define ROWLEN  148      // j' range: 0..147 (j in 0..127, dj in 0..20)
#define ROWPAD  152      // padded to 16B-aligned stride

__global__ __launch_bounds__(THREADS)
void corr_kernel(const float* __restrict__ x1,
                 const float* __restrict__ x2,
                 float* __restrict__ out)
{
    __shared__ float s_x1[NWARP][KC][ROWPAD]; // 7*8*152*4 = 34048 B
    __shared__ float s_x2[KC][H_];            // 8*128*4   =  4096 B

    const int dig = blockIdx.x;   // 0..2  -> di group
    const int i   = blockIdx.y;   // 0..127
    const int b   = blockIdx.z;   // 0..3
    const int di0 = dig * NWARP;

    const int tid  = threadIdx.x;
    const int warp = tid >> 5;    // 0..6 -> di = di0 + warp
    const int lane = tid & 31;    // j0 = 4*lane

    // x1 source row for this warp's displacement (padded coords)
    const int row = i + di0 + warp - PADN;
    const bool rowok = (row >= 0) && (row < W_);

    float acc[DWIN][4];
#pragma unroll
    for (int dj = 0; dj < DWIN; dj++) {
        acc[dj][0] = 0.f; acc[dj][1] = 0.f; acc[dj][2] = 0.f; acc[dj][3] = 0.f;
    }

    const float* x1b = x1 + (size_t)b * C_ * W_ * H_;
    const float* x2b = x2 + (size_t)b * C_ * W_ * H_ + (size_t)i * H_;

    for (int c0 = 0; c0 < C_; c0 += KC) {
        __syncthreads();  // previous compute phase done before overwriting smem

        // ---- stage x1: warp w loads its row (zero-padded to 148 cols) ----
        {
            const float* src = x1b + ((size_t)c0 * W_ + row) * H_;
#pragma unroll
            for (int c = 0; c < KC; c++) {
                const float* srcc = src + (size_t)c * (W_ * H_);
                for (int jp = lane; jp < ROWLEN; jp += 32) {
                    const int col = jp - PADN;
                    float v = 0.f;
                    if (rowok && col >= 0 && col < H_) v = srcc[col];
                    s_x1[warp][c][jp] = v;
                }
            }
        }
        // ---- stage x2 row chunk: KC*128 floats, vectorized ----
        for (int idx = tid; idx < KC * (H_ / 4); idx += THREADS) {
            const int c  = idx >> 5;      // H_/4 = 32
            const int jv = idx & 31;
            ((float4*)s_x2[c])[jv] =
                ((const float4*)(x2b + (size_t)(c0 + c) * (W_ * H_)))[jv];
        }
        __syncthreads();

        // ---- compute: 84 FMAs per channel per thread ----
#pragma unroll
        for (int c = 0; c < KC; c++) {
            const float* xr = &s_x1[warp][c][0] + 4 * lane;
            float w[24];
#pragma unroll
            for (int k = 0; k < 6; k++) {
                const float4 t = *(const float4*)(xr + 4 * k);
                w[4*k+0] = t.x; w[4*k+1] = t.y; w[4*k+2] = t.z; w[4*k+3] = t.w;
            }
            const float4 bv = *(const float4*)(&s_x2[c][4 * lane]);
#pragma unroll
            for (int dj = 0; dj < DWIN; dj++) {
                acc[dj][0] += w[dj+0] * bv.x;
                acc[dj][1] += w[dj+1] * bv.y;
                acc[dj][2] += w[dj+2] * bv.z;
                acc[dj][3] += w[dj+3] * bv.w;
            }
        }
    }

    // ---- write out[b, (di0+warp)*21+dj, i, 4*lane .. +3] ----
    const int di = di0 + warp;
    float* ob = out + (((size_t)b * (DWIN * DWIN) + (size_t)di * DWIN) * W_ + i) * H_
                    + 4 * lane;
#pragma unroll
    for (int dj = 0; dj < DWIN; dj++) {
        float4 v = make_float4(acc[dj][0], acc[dj][1], acc[dj][2], acc[dj][3]);
        *(float4*)(ob + (size_t)dj * (W_ * H_)) = v;
    }
}

extern "C" void kernel_launch(void* const* d_in, const int* in_sizes, int n_in,
                              void* d_out, int out_size)
{
    const float* x1 = (const float*)d_in[0];
    const float* x2 = (const float*)d_in[1];
    float* out = (float*)d_out;

    dim3 grid(3, W_, B_);   // (di group, i, b)
    corr_kernel<<<grid, THREADS>>>(x1, x2, out);
}

// round 3
// speedup vs baseline: 3.7621x; 3.7621x over previous
#include <cuda_runtime.h>

#define B_    4
#define C_    128
#define W_    128
#define H_    128
#define DWIN  21
#define PADN  10
#define KC    8           // channels staged per smem chunk
#define NWARP 7           // di values per block (one per warp)
#define THREADS (NWARP * 32)
#define JBLK   64         // j columns per block (half row)
#define ROWLEN (JBLK + 2 * PADN)  // 84 staged cols per row
#define ROWPAD 88                  // padded stride (8B align kept everywhere)

__global__ __launch_bounds__(THREADS, 3)
void corr_kernel(const float* __restrict__ x1,
                 const float* __restrict__ x2,
                 float* __restrict__ out)
{
    __shared__ float s_x1[NWARP][KC][ROWPAD]; // 7*8*88*4  = 19712 B
    __shared__ float s_x2[KC][JBLK];          // 8*64*4    =  2048 B

    const int bx    = blockIdx.x;      // 0..5 : dig*2 + jhalf
    const int dig   = bx >> 1;         // 0..2
    const int jhalf = bx & 1;          // 0..1
    const int i     = blockIdx.y;      // 0..127
    const int b     = blockIdx.z;      // 0..3
    const int di0   = dig * NWARP;
    const int j0blk = jhalf * JBLK;

    const int tid  = threadIdx.x;
    const int warp = tid >> 5;         // di = di0 + warp
    const int lane = tid & 31;         // j = j0blk + 2*lane + {0,1}

    const int row   = i + di0 + warp - PADN;   // x1 source row (unpadded)
    const bool rowok = (row >= 0) && (row < W_);

    float acc[DWIN][2];
#pragma unroll
    for (int dj = 0; dj < DWIN; dj++) { acc[dj][0] = 0.f; acc[dj][1] = 0.f; }

    const float* x1b = x1 + (size_t)b * C_ * W_ * H_;
    const float* x2b = x2 + (size_t)b * C_ * W_ * H_ + (size_t)i * H_ + j0blk;

    for (int c0 = 0; c0 < C_; c0 += KC) {
        __syncthreads();   // previous compute done before restaging

        // ---- stage x1: warp w stages its displaced row, cols j0blk-10 .. j0blk+73 ----
        {
            const float* src = x1b + ((size_t)c0 * W_ + row) * H_;
#pragma unroll
            for (int c = 0; c < KC; c++) {
                const float* srcc = src + (size_t)c * (W_ * H_);
#pragma unroll
                for (int it = 0; it < 3; it++) {          // 3*32 >= 84
                    const int jp = it * 32 + lane;
                    if (jp < ROWLEN) {
                        const int col = j0blk + jp - PADN;
                        float v = 0.f;
                        if (rowok && col >= 0 && col < H_) v = srcc[col];
                        s_x1[warp][c][jp] = v;
                    }
                }
            }
        }
        // ---- stage x2 chunk: KC*64 floats = 128 float4, one per thread ----
        if (tid < KC * (JBLK / 4)) {
            const int c  = tid >> 4;          // JBLK/4 = 16
            const int jv = tid & 15;
            ((float4*)s_x2[c])[jv] =
                ((const float4*)(x2b + (size_t)(c0 + c) * (W_ * H_)))[jv];
        }
        __syncthreads();

        // ---- compute: 42 FMAs per channel per thread ----
#pragma unroll
        for (int c = 0; c < KC; c++) {
            const float* xr = &s_x1[warp][c][2 * lane];
            float w[22];
#pragma unroll
            for (int k = 0; k < 11; k++) {
                const float2 t = *(const float2*)(xr + 2 * k);
                w[2*k]   = t.x;
                w[2*k+1] = t.y;
            }
            const float2 bv = *(const float2*)(&s_x2[c][2 * lane]);
#pragma unroll
            for (int dj = 0; dj < DWIN; dj++) {
                acc[dj][0] += w[dj]     * bv.x;
                acc[dj][1] += w[dj + 1] * bv.y;
            }
        }
    }

    // ---- write out[b, (di0+warp)*21+dj, i, j0blk+2*lane .. +1] ----
    const int di = di0 + warp;
    float* ob = out + (((size_t)b * (DWIN * DWIN) + (size_t)di * DWIN) * W_ + i) * H_
                    + j0blk + 2 * lane;
#pragma unroll
    for (int dj = 0; dj < DWIN; dj++) {
        *(float2*)(ob + (size_t)dj * (W_ * H_)) = make_float2(acc[dj][0], acc[dj][1]);
    }
}

extern "C" void kernel_launch(void* const* d_in, const int* in_sizes, int n_in,
                              void* d_out, int out_size)
{
    const float* x1 = (const float*)d_in[0];
    const float* x2 = (const float*)d_in[1];
    float* out = (float*)d_out;

    dim3 grid(6, W_, B_);   // (dig*2 + jhalf, i, b)
    corr_kernel<<<grid, THREADS>>>(x1, x2, out);
}

// round 5
// speedup vs baseline: 6.7630x; 1.7977x over previous
#include <cuda_runtime.h>

#define B_    4
#define C_    128
#define W_    128
#define H_    128
#define DWIN  21
#define PADN  10
#define KC    4                    // channels per staged chunk
#define NWARP 7
#define THREADS (NWARP * 32)
#define JBLK   64
#define SHIFT  12                  // staged x1 window starts at col j0blk-12 (16B aligned)
#define ROWLEN 88                  // 22 float4 groups
#define NG1    (ROWLEN / 4)        // 22
#define NCHUNK (C_ / KC)           // 32

__global__ __launch_bounds__(THREADS, 3)
void corr_kernel(const float* __restrict__ x1,
                 const float* __restrict__ x2,
                 float* __restrict__ out)
{
    __shared__ __align__(16) float s_x1[NWARP][KC][ROWLEN]; // 7*4*88*4 = 9856 B
    __shared__ __align__(16) float s_x2[KC][JBLK];          // 4*64*4   = 1024 B

    const int bx    = blockIdx.x;      // dig*2 + jhalf
    const int dig   = bx >> 1;
    const int jhalf = bx & 1;
    const int i     = blockIdx.y;
    const int b     = blockIdx.z;
    const int di0   = dig * NWARP;
    const int j0blk = jhalf * JBLK;

    const int tid  = threadIdx.x;
    const int warp = tid >> 5;         // di = di0 + warp
    const int lane = tid & 31;         // j = j0blk + 2*lane + {0,1}

    const int row   = i + di0 + warp - PADN;
    const bool rowok = (row >= 0) && (row < W_);

    const float* x1b = x1 + (size_t)b * C_ * W_ * H_;
    const float* x2b = x2 + (size_t)b * C_ * W_ * H_ + (size_t)i * H_ + j0blk;

    // x1 staging: lane g (<22) owns float4 group g (cols j0blk-12+4g) of each channel
    const int col0  = j0blk - SHIFT + 4 * lane;
    const bool g1ok = rowok && (lane < NG1) && (col0 >= 0) && (col0 < H_);
    const float* g1src = x1b + (size_t)row * H_ + col0;   // deref only if g1ok
    // x2 staging: threads 0..63 own one float4 group
    const int x2c = tid >> 4;          // 0..3 (valid when tid < 64)
    const int x2g = tid & 15;
    const bool g2ok = (tid < KC * (JBLK / 4));
    const float* g2src = x2b + (size_t)x2c * (W_ * H_) + 4 * x2g;

    float acc[DWIN][2];
#pragma unroll
    for (int dj = 0; dj < DWIN; dj++) { acc[dj][0] = 0.f; acc[dj][1] = 0.f; }

    float4 r1[KC];
    float4 r2;

    // ---- prologue: load chunk 0 into registers ----
#pragma unroll
    for (int c = 0; c < KC; c++)
        r1[c] = g1ok ? *(const float4*)(g1src + (size_t)c * (W_ * H_))
                     : make_float4(0.f, 0.f, 0.f, 0.f);
    r2 = g2ok ? *(const float4*)g2src : make_float4(0.f, 0.f, 0.f, 0.f);

    for (int k = 0; k < NCHUNK; k++) {
        __syncthreads();   // all threads done computing from smem (chunk k-1)

        // ---- store staged registers (chunk k) to smem ----
        if (lane < NG1) {
#pragma unroll
            for (int c = 0; c < KC; c++)
                *(float4*)(&s_x1[warp][c][4 * lane]) = r1[c];
        }
        if (g2ok)
            *(float4*)(&s_x2[x2c][4 * x2g]) = r2;
        __syncthreads();

        // ---- prefetch chunk k+1 into registers (completes during compute) ----
        if (k + 1 < NCHUNK) {
            const size_t coff = (size_t)(k + 1) * KC * (W_ * H_);
#pragma unroll
            for (int c = 0; c < KC; c++)
                r1[c] = g1ok ? *(const float4*)(g1src + coff + (size_t)c * (W_ * H_))
                             : make_float4(0.f, 0.f, 0.f, 0.f);
            r2 = g2ok ? *(const float4*)(g2src + coff) : make_float4(0.f, 0.f, 0.f, 0.f);
        }

        // ---- compute chunk k: 42 FMAs per channel per thread ----
#pragma unroll
        for (int c = 0; c < KC; c++) {
            // staged col p <-> global col j0blk - 12 + p; need j0blk + 2*lane - 10 + dj
            const float* xr = &s_x1[warp][c][2 * lane + (SHIFT - PADN)];
            float w[22];
#pragma unroll
            for (int t = 0; t < 11; t++) {
                const float2 v = *(const float2*)(xr + 2 * t);
                w[2*t]   = v.x;
                w[2*t+1] = v.y;
            }
            const float2 bv = *(const float2*)(&s_x2[c][2 * lane]);
#pragma unroll
            for (int dj = 0; dj < DWIN; dj++) {
                acc[dj][0] += w[dj]     * bv.x;
                acc[dj][1] += w[dj + 1] * bv.y;
            }
        }
    }

    // ---- write out[b, (di0+warp)*21+dj, i, j0blk+2*lane .. +1] ----
    const int di = di0 + warp;
    float* ob = out + (((size_t)b * (DWIN * DWIN) + (size_t)di * DWIN) * W_ + i) * H_
                    + j0blk + 2 * lane;
#pragma unroll
    for (int dj = 0; dj < DWIN; dj++) {
        *(float2*)(ob + (size_t)dj * (W_ * H_)) = make_float2(acc[dj][0], acc[dj][1]);
    }
}

extern "C" void kernel_launch(void* const* d_in, const int* in_sizes, int n_in,
                              void* d_out, int out_size)
{
    const float* x1 = (const float*)d_in[0];
    const float* x2 = (const float*)d_in[1];
    float* out = (float*)d_out;

    dim3 grid(6, W_, B_);   // (dig*2 + jhalf, i, b)
    corr_kernel<<<grid, THREADS>>>(x1, x2, out);
}